// round 9
// baseline (speedup 1.0000x reference)
#include <cuda_runtime.h>
#include <cstdint>

#define NQ      12
#define DIM     4096      // 2^12 amplitudes
#define THREADS 256
#define BATCH   4096
#define FEAT    768
#define NCLASS  10

// ---- compile-time GF(2) composites of the fixed CNOT rings ----
__device__ __constant__ const int C0T[8] = {0x81F,0x83F,0x87F,0x8FF,0x9FF,0xBFF,0xFFF,0x7FF};
static __device__ __constant__ const int SLOTK0[16] = {
    0x000,0x801,0x803,0x002,0x807,0x006,0x004,0x805,
    0x80F,0x00E,0x00C,0x80D,0x008,0x809,0x80B,0x00A};
__device__ __constant__ const int C1T[8] = {0x401,0x802,0x405,0x80A,0x415,0x82A,0x455,0x8AA};
static __device__ __constant__ const int SLOTK1[16] = {
    0x000,0x550,0xAA0,0xFF0,0x150,0x400,0xBF0,0xEA0,
    0x2A0,0x7F0,0x800,0xD50,0x3F0,0x6A0,0x950,0xC00};
// layer-2 measurement masks -> Walsh coeffs {0,1,2,4,9}.

// ---- real RY gate sweep: 4 gates on local bits 0..3 (8 FMA per pair) ----
template <int STAGE>
__device__ __forceinline__ void apply4r(float2 amp[16], const float2 (&ry)[24], int lbase) {
#pragma unroll
    for (int g = 0; g < 4; ++g) {
        const int wire = 11 - (STAGE * 4 + g);
        const float2 m = ry[lbase + wire];
        const float c = m.x, s = m.y;
        const int mask = 1 << g;
#pragma unroll
        for (int k = 0; k < 8; ++k) {
            const int h  = ((k & ~(mask - 1)) << 1) | (k & (mask - 1));
            const int h2 = h | mask;
            const float2 a = amp[h], b2 = amp[h2];
            amp[h].x  = c * a.x - s * b2.x;
            amp[h].y  = c * a.y - s * b2.y;
            amp[h2].x = s * a.x + c * b2.x;
            amp[h2].y = s * a.y + c * b2.y;
        }
    }
}

// ---- product-diagonal application at a direct-index point ----
__device__ __forceinline__ void apply_diag(float2 amp[16], const float2* Zv,
                                           const float* angT, int t) {
    float a = 0.f;
#pragma unroll
    for (int k = 0; k < 8; ++k) a += ((t >> k) & 1) ? angT[k] : 0.f;
    float zr, zi; __sincosf(a, &zi, &zr);
#pragma unroll
    for (int v = 0; v < 16; ++v) {
        const float2 z = Zv[v];                 // broadcast LDS
        const float wr = zr * z.x - zi * z.y;
        const float wi = zr * z.y + zi * z.x;
        const float nx = amp[v].x * wr - amp[v].y * wi;
        amp[v].y = amp[v].x * wi + amp[v].y * wr;
        amp[v].x = nx;
    }
}

__global__ __launch_bounds__(THREADS, 4)
void qhead_kernel(const float* __restrict__ x,
                  const float* __restrict__ Wp,
                  const float* __restrict__ weights,
                  const float* __restrict__ Wo,
                  const float* __restrict__ bo,
                  float* __restrict__ out)
{
    __shared__ float2 st[DIM];          // swizzled state: slot(p) = p ^ ((p>>4)&15)
    __shared__ float2 cs[NQ];           // (cos(a/2), sin(a/2)) per wire
    __shared__ float  rot0[NQ][8];      // layer-0 Rot matrices (for init fold only)
    __shared__ float4 Fm[NQ];           // merged per-wire factor Rot0 * RY(a) |0>
    __shared__ float2 ry[24];           // (cos(th/2), sin(th/2)) for layers 1,2
    __shared__ float2 Zv[3][16];        // diagonal v-part tables (incl. base phase)
    __shared__ float  angT[3][8];       // diagonal t-part angles
    __shared__ float  red[8][NQ];       // cross-warp reduction buffer

    const int t    = threadIdx.x;
    const int b    = blockIdx.x;
    const int lane = t & 31;
    const int warp = t >> 5;

    // ---- angle encoding: 12 dot products (float4), tanh, half-angle sincos ----
    {
        const float4* xr4  = (const float4*)(x + (size_t)b * FEAT);
        const int q0 = warp;
        const bool two = (warp < 4);
        const float4* wp04 = (const float4*)(Wp + q0 * FEAT);
        const float4* wp14 = (const float4*)(Wp + (q0 + 8) * FEAT);
        float d0 = 0.f, d1 = 0.f;
#pragma unroll
        for (int i = lane; i < FEAT / 4; i += 32) {
            const float4 xv = xr4[i];
            const float4 a  = wp04[i];
            d0 += xv.x * a.x + xv.y * a.y + xv.z * a.z + xv.w * a.w;
            if (two) {
                const float4 c = wp14[i];
                d1 += xv.x * c.x + xv.y * c.y + xv.z * c.z + xv.w * c.w;
            }
        }
#pragma unroll
        for (int o = 16; o; o >>= 1) {
            d0 += __shfl_xor_sync(0xffffffffu, d0, o);
            d1 += __shfl_xor_sync(0xffffffffu, d1, o);
        }
        if (lane == 0) {
            float th = tanhf(d0) * 0.7853981633974483f;   // a/2
            float c, s; __sincosf(th, &s, &c);
            cs[q0] = make_float2(c, s);
            if (two) {
                float th1 = tanhf(d1) * 0.7853981633974483f;
                float c1, s1; __sincosf(th1, &s1, &c1);
                cs[q0 + 8] = make_float2(c1, s1);
            }
        }
    }

    // ---- layer-0 Rot matrices (full, for init fold) ----
    if (t < NQ) {
        const float phi = weights[t * 3 + 0];
        const float th  = weights[t * 3 + 1];
        const float om  = weights[t * 3 + 2];
        float c, s; __sincosf(0.5f * th, &s, &c);
        const float aa = 0.5f * (phi + om);
        const float bb = 0.5f * (phi - om);
        float sa, ca, sb, cb;
        __sincosf(aa, &sa, &ca);
        __sincosf(bb, &sb, &cb);
        rot0[t][0] =  c * ca;  rot0[t][1] = -c * sa;   // m00
        rot0[t][2] = -s * cb;  rot0[t][3] = -s * sb;   // m01
        rot0[t][4] =  s * cb;  rot0[t][5] = -s * sb;   // m10
        rot0[t][6] =  c * ca;  rot0[t][7] =  c * sa;   // m11
    }

    // ---- RY half-angle (c,s) for layers 1,2 ----
    if (t < 24) {
        const int l = 1 + t / 12, q = t % 12;
        const float th = weights[(l * 12 + q) * 3 + 1];
        float c, s; __sincosf(0.5f * th, &s, &c);
        ry[t] = make_float2(c, s);
    }

    // ---- diagonal tables: d=0 -> phi(l1), d=1 -> omega(l1), d=2 -> phi(l2) ----
    if (t < 48) {
        const int d = t >> 4, v = t & 15;
        const int l = (d == 2) ? 2 : 1;
        const int j = (d == 1) ? 2 : 0;
        float ang[12];
        float sum = 0.f;
#pragma unroll
        for (int q = 0; q < 12; ++q) { ang[q] = weights[(l * 12 + q) * 3 + j]; sum += ang[q]; }
        float a = -0.5f * sum;
#pragma unroll
        for (int m = 0; m < 4; ++m)
            if ((v >> m) & 1) a += (d == 1) ? ang[3 - m] : ang[11 - m];
        float zr, zi; __sincosf(a, &zi, &zr);
        Zv[d][v] = make_float2(zr, zi);
        if (v < 8) angT[d][v] = (d == 1) ? ang[11 - v] : ang[7 - v];
    }
    __syncthreads();

    // ---- merged per-wire factor: F = Rot0_q * (cos, sin)^T ----
    if (t < NQ) {
        const float c = cs[t].x, s = cs[t].y;
        const float* m = rot0[t];
        Fm[t] = make_float4(m[0] * c + m[2] * s,
                            m[1] * c + m[3] * s,
                            m[4] * c + m[6] * s,
                            m[5] * c + m[7] * s);
    }
    __syncthreads();

    // ---- init: post-layer0 product state scattered through layer-0 CNOT ring ----
    {
        float br, bi;
        {
            const float4 f = Fm[7];
            br = (t & 1) ? f.z : f.x;
            bi = (t & 1) ? f.w : f.y;
        }
#pragma unroll
        for (int k = 1; k < 8; ++k) {
            const float4 f = Fm[7 - k];
            const float fr = ((t >> k) & 1) ? f.z : f.x;
            const float fi = ((t >> k) & 1) ? f.w : f.y;
            const float nbr = br * fr - bi * fi;
            bi = br * fi + bi * fr;
            br = nbr;
        }
        float lr[4], li[4], hr[4], hi4[4];
        {
            const float4 fA = Fm[11], fB = Fm[10], fC = Fm[9], fD = Fm[8];
#pragma unroll
            for (int j = 0; j < 4; ++j) {
                const float ar = (j & 1) ? fA.z : fA.x, ai = (j & 1) ? fA.w : fA.y;
                const float br2 = (j & 2) ? fB.z : fB.x, bi2 = (j & 2) ? fB.w : fB.y;
                lr[j] = ar * br2 - ai * bi2;
                li[j] = ar * bi2 + ai * br2;
                const float cr = (j & 1) ? fC.z : fC.x, ci = (j & 1) ? fC.w : fC.y;
                const float dr = (j & 2) ? fD.z : fD.x, di = (j & 2) ? fD.w : fD.y;
                hr[j] = cr * dr - ci * di;
                hi4[j] = cr * di + ci * dr;
            }
        }
        int dT = 0;
#pragma unroll
        for (int k = 0; k < 8; ++k) dT ^= ((t >> k) & 1) ? C0T[k] : 0;
        const int sb0 = dT ^ ((dT >> 4) & 15);
#pragma unroll
        for (int v = 0; v < 16; ++v) {
            const float plr = lr[v & 3], pli = li[v & 3];
            const float phr = hr[v >> 2], phi2 = hi4[v >> 2];
            const float tr = plr * phr - pli * phi2;
            const float ti = plr * phi2 + pli * phr;
            st[sb0 ^ SLOTK0[v]] = make_float2(br * tr - bi * ti, br * ti + bi * tr);
        }
    }
    __syncthreads();

    float2 amp[16];

    // ===================== layer 1 =====================
    {   // stage A: p = t<<4 | v.  Dphi1 then RY wires 11..8
        const int base = t * 16, x4 = t & 15;
#pragma unroll
        for (int v = 0; v < 16; ++v) amp[v] = st[base + (v ^ x4)];
        apply_diag(amp, Zv[0], angT[0], t);
        apply4r<0>(amp, ry, 0);
#pragma unroll
        for (int v = 0; v < 16; ++v) st[base + (v ^ x4)] = amp[v];
    }
    __syncthreads();
    {   // stage B: RY wires 7..4
        const int hi = (t >> 4) * 256, x4 = t & 15;
#pragma unroll
        for (int v = 0; v < 16; ++v) amp[v] = st[hi + v * 16 + (x4 ^ v)];
        apply4r<1>(amp, ry, 0);
#pragma unroll
        for (int v = 0; v < 16; ++v) st[hi + v * 16 + (x4 ^ v)] = amp[v];
    }
    __syncthreads();
    {   // stage C: p = t | v<<8. RY wires 3..0, then Domega1, then C1 scatter
        const int slo = t ^ (t >> 4);
#pragma unroll
        for (int v = 0; v < 16; ++v) amp[v] = st[v * 256 + slo];
        apply4r<2>(amp, ry, 0);
        apply_diag(amp, Zv[1], angT[1], t);
        __syncthreads();
        int dT = 0;
#pragma unroll
        for (int j = 0; j < 8; ++j) dT ^= ((t >> j) & 1) ? C1T[j] : 0;
        const int sb1 = dT ^ ((dT >> 4) & 15);
#pragma unroll
        for (int v = 0; v < 16; ++v)
            st[sb1 ^ SLOTK1[v]] = amp[v];
        __syncthreads();
    }

    // ===================== layer 2 =====================
    {   // stage A: Dphi2 then RY wires 11..8
        const int base = t * 16, x4 = t & 15;
#pragma unroll
        for (int v = 0; v < 16; ++v) amp[v] = st[base + (v ^ x4)];
        apply_diag(amp, Zv[2], angT[2], t);
        apply4r<0>(amp, ry, 12);
#pragma unroll
        for (int v = 0; v < 16; ++v) st[base + (v ^ x4)] = amp[v];
    }
    __syncthreads();
    {   // stage B
        const int hi = (t >> 4) * 256, x4 = t & 15;
#pragma unroll
        for (int v = 0; v < 16; ++v) amp[v] = st[hi + v * 16 + (x4 ^ v)];
        apply4r<1>(amp, ry, 12);
#pragma unroll
        for (int v = 0; v < 16; ++v) st[hi + v * 16 + (x4 ^ v)] = amp[v];
    }
    __syncthreads();
    {   // stage C: RY wires 3..0; amps stay in regs (Domega2 dropped; C2 folded
        //          into measurement parity masks)
        const int slo = t ^ (t >> 4);
#pragma unroll
        for (int v = 0; v < 16; ++v) amp[v] = st[v * 256 + slo];
        apply4r<2>(amp, ry, 12);
    }

    // ---- probs in place ----
#pragma unroll
    for (int v = 0; v < 16; ++v)
        amp[v].x = amp[v].x * amp[v].x + amp[v].y * amp[v].y;

    // ---- PauliZ expectations via 5 Walsh coefficients of per-thread probs ----
    const float Pe = ((amp[0].x + amp[2].x) + (amp[4].x + amp[6].x))
                   + ((amp[8].x + amp[10].x) + (amp[12].x + amp[14].x));
    const float Po = ((amp[1].x + amp[3].x) + (amp[5].x + amp[7].x))
                   + ((amp[9].x + amp[11].x) + (amp[13].x + amp[15].x));
    const float w0 = Pe + Po;
    const float w1 = Pe - Po;
    const float A  = ((amp[0].x + amp[1].x) + (amp[4].x + amp[5].x))
                   + ((amp[8].x + amp[9].x) + (amp[12].x + amp[13].x));
    const float w2 = 2.f * A - w0;
    const float Bb = ((amp[0].x + amp[1].x) + (amp[2].x + amp[3].x))
                   + ((amp[8].x + amp[9].x) + (amp[10].x + amp[11].x));
    const float w4 = 2.f * Bb - w0;
    const float Cc = ((amp[0].x + amp[2].x) + (amp[4].x + amp[6].x))
                   + ((amp[9].x + amp[11].x) + (amp[13].x + amp[15].x));
    const float w9 = 2.f * Cc - w0;

    const int t0 = t & 1, t1 = (t >> 1) & 1, t2 = (t >> 2) & 1, t3 = (t >> 3) & 1;
    const int t4 = (t >> 4) & 1, t5 = (t >> 5) & 1, t6 = (t >> 6) & 1, t7 = (t >> 7) & 1;
    const int s24 = t2 ^ t5;
    const int s92 = t1 ^ t4 ^ t7;
    const int s49 = t0 ^ t3 ^ t6;
    const int s90 = t4 ^ t7;
    const int s48 = t3 ^ t6;

    float acc[NQ];
    acc[0]  = s24 ? -w1 : w1;
    acc[1]  = s92 ? -w0 : w0;
    acc[2]  = s49 ? -w0 : w0;
    acc[3]  = w9;
    acc[4]  = t7  ? -w4 : w4;
    acc[5]  = t6  ? -w2 : w2;
    acc[6]  = t5  ? -w9 : w9;
    acc[7]  = s90 ? -w4 : w4;
    acc[8]  = s48 ? -w2 : w2;
    acc[9]  = s24 ? -w9 : w9;
    acc[10] = s92 ? -w4 : w4;
    acc[11] = s49 ? -w2 : w2;

#pragma unroll
    for (int q = 0; q < NQ; ++q) {
        float vq = acc[q];
#pragma unroll
        for (int o = 16; o; o >>= 1) vq += __shfl_xor_sync(0xffffffffu, vq, o);
        if (lane == 0) red[warp][q] = vq;
    }
    __syncthreads();

    // ---- output head ----
    if (t < NCLASS) {
        float o = bo[t];
#pragma unroll
        for (int q = 0; q < NQ; ++q) {
            float z = 0.f;
#pragma unroll
            for (int w = 0; w < 8; ++w) z += red[w][q];
            o += z * Wo[t * NQ + q];
        }
        out[(size_t)b * NCLASS + t] = o;
    }
}

extern "C" void kernel_launch(void* const* d_in, const int* in_sizes, int n_in,
                              void* d_out, int out_size) {
    (void)in_sizes; (void)n_in; (void)out_size;
    const float* x       = (const float*)d_in[0];
    const float* Wp      = (const float*)d_in[1];
    const float* weights = (const float*)d_in[2];
    const float* Wo      = (const float*)d_in[3];
    const float* bo      = (const float*)d_in[4];

    qhead_kernel<<<BATCH, THREADS>>>(x, Wp, weights, Wo, bo, (float*)d_out);
}

// round 10
// speedup vs baseline: 1.0005x; 1.0005x over previous
#include <cuda_runtime.h>
#include <cstdint>

#define NQ      12
#define DIM     4096      // 2^12 amplitudes
#define THREADS 256
#define BATCH   4096
#define FEAT    768
#define NCLASS  10

// ---- compile-time GF(2) composites of the fixed CNOT rings ----
__device__ __constant__ const int C0T[8] = {0x81F,0x83F,0x87F,0x8FF,0x9FF,0xBFF,0xFFF,0x7FF};
static __device__ __constant__ const int SLOTK0[16] = {
    0x000,0x801,0x803,0x002,0x807,0x006,0x004,0x805,
    0x80F,0x00E,0x00C,0x80D,0x008,0x809,0x80B,0x00A};
__device__ __constant__ const int C1T[8] = {0x401,0x802,0x405,0x80A,0x415,0x82A,0x455,0x8AA};
static __device__ __constant__ const int SLOTK1[16] = {
    0x000,0x550,0xAA0,0xFF0,0x150,0x400,0xBF0,0xEA0,
    0x2A0,0x7F0,0x800,0xD50,0x3F0,0x6A0,0x950,0xC00};
// layer-2 measurement masks -> Walsh coeffs {0,1,2,4,9}.

// ---- real RY gate sweep: 4 gates on local bits 0..3 (8 FMA per pair) ----
template <int STAGE>
__device__ __forceinline__ void apply4r(float2 amp[16], const float2 (&ry)[24], int lbase) {
#pragma unroll
    for (int g = 0; g < 4; ++g) {
        const int wire = 11 - (STAGE * 4 + g);
        const float2 m = ry[lbase + wire];
        const float c = m.x, s = m.y;
        const int mask = 1 << g;
#pragma unroll
        for (int k = 0; k < 8; ++k) {
            const int h  = ((k & ~(mask - 1)) << 1) | (k & (mask - 1));
            const int h2 = h | mask;
            const float2 a = amp[h], b2 = amp[h2];
            amp[h].x  = c * a.x - s * b2.x;
            amp[h].y  = c * a.y - s * b2.y;
            amp[h2].x = s * a.x + c * b2.x;
            amp[h2].y = s * a.y + c * b2.y;
        }
    }
}

// ---- product-diagonal application at a direct-index point ----
__device__ __forceinline__ void apply_diag(float2 amp[16], const float2* Zv,
                                           const float* angT, int t) {
    float a = 0.f;
#pragma unroll
    for (int k = 0; k < 8; ++k) a += ((t >> k) & 1) ? angT[k] : 0.f;
    float zr, zi; __sincosf(a, &zi, &zr);
#pragma unroll
    for (int v = 0; v < 16; ++v) {
        const float2 z = Zv[v];                 // broadcast LDS
        const float wr = zr * z.x - zi * z.y;
        const float wi = zr * z.y + zi * z.x;
        const float nx = amp[v].x * wr - amp[v].y * wi;
        amp[v].y = amp[v].x * wi + amp[v].y * wr;
        amp[v].x = nx;
    }
}

__global__ __launch_bounds__(THREADS, 4)
void qhead_kernel(const float* __restrict__ x,
                  const float* __restrict__ Wp,
                  const float* __restrict__ weights,
                  const float* __restrict__ Wo,
                  const float* __restrict__ bo,
                  float* __restrict__ out)
{
    __shared__ float2 st[DIM];          // swizzled state: slot(p) = p ^ ((p>>4)&15)
    __shared__ float2 cs[NQ];           // (cos(a/2), sin(a/2)) per wire
    __shared__ float  rot0[NQ][8];      // layer-0 Rot matrices (for init fold only)
    __shared__ float4 Fm[NQ];           // merged per-wire factor Rot0 * RY(a) |0>
    __shared__ float2 ry[24];           // (cos(th/2), sin(th/2)) for layers 1,2
    __shared__ float2 Zv[3][16];        // diagonal v-part tables (incl. base phase)
    __shared__ float  angT[3][8];       // diagonal t-part angles
    __shared__ float  red[8][NQ];       // cross-warp reduction buffer

    const int t    = threadIdx.x;
    const int b    = blockIdx.x;
    const int lane = t & 31;
    const int warp = t >> 5;

    // ---- angle encoding: 12 dot products (float4), tanh, half-angle sincos ----
    {
        const float4* xr4  = (const float4*)(x + (size_t)b * FEAT);
        const int q0 = warp;
        const bool two = (warp < 4);
        const float4* wp04 = (const float4*)(Wp + q0 * FEAT);
        const float4* wp14 = (const float4*)(Wp + (q0 + 8) * FEAT);
        float d0 = 0.f, d1 = 0.f;
#pragma unroll
        for (int i = lane; i < FEAT / 4; i += 32) {
            const float4 xv = xr4[i];
            const float4 a  = wp04[i];
            d0 += xv.x * a.x + xv.y * a.y + xv.z * a.z + xv.w * a.w;
            if (two) {
                const float4 c = wp14[i];
                d1 += xv.x * c.x + xv.y * c.y + xv.z * c.z + xv.w * c.w;
            }
        }
#pragma unroll
        for (int o = 16; o; o >>= 1) {
            d0 += __shfl_xor_sync(0xffffffffu, d0, o);
            d1 += __shfl_xor_sync(0xffffffffu, d1, o);
        }
        if (lane == 0) {
            float th = tanhf(d0) * 0.7853981633974483f;   // a/2
            float c, s; __sincosf(th, &s, &c);
            cs[q0] = make_float2(c, s);
            if (two) {
                float th1 = tanhf(d1) * 0.7853981633974483f;
                float c1, s1; __sincosf(th1, &s1, &c1);
                cs[q0 + 8] = make_float2(c1, s1);
            }
        }
    }

    // ---- layer-0 Rot matrices (full, for init fold) ----
    if (t < NQ) {
        const float phi = weights[t * 3 + 0];
        const float th  = weights[t * 3 + 1];
        const float om  = weights[t * 3 + 2];
        float c, s; __sincosf(0.5f * th, &s, &c);
        const float aa = 0.5f * (phi + om);
        const float bb = 0.5f * (phi - om);
        float sa, ca, sb, cb;
        __sincosf(aa, &sa, &ca);
        __sincosf(bb, &sb, &cb);
        rot0[t][0] =  c * ca;  rot0[t][1] = -c * sa;   // m00
        rot0[t][2] = -s * cb;  rot0[t][3] = -s * sb;   // m01
        rot0[t][4] =  s * cb;  rot0[t][5] = -s * sb;   // m10
        rot0[t][6] =  c * ca;  rot0[t][7] =  c * sa;   // m11
    }

    // ---- RY half-angle (c,s) for layers 1,2 ----
    if (t < 24) {
        const int l = 1 + t / 12, q = t % 12;
        const float th = weights[(l * 12 + q) * 3 + 1];
        float c, s; __sincosf(0.5f * th, &s, &c);
        ry[t] = make_float2(c, s);
    }

    // ---- diagonal tables: d=0 -> phi(l1), d=1 -> omega(l1), d=2 -> phi(l2) ----
    if (t < 48) {
        const int d = t >> 4, v = t & 15;
        const int l = (d == 2) ? 2 : 1;
        const int j = (d == 1) ? 2 : 0;
        float ang[12];
        float sum = 0.f;
#pragma unroll
        for (int q = 0; q < 12; ++q) { ang[q] = weights[(l * 12 + q) * 3 + j]; sum += ang[q]; }
        float a = -0.5f * sum;
#pragma unroll
        for (int m = 0; m < 4; ++m)
            if ((v >> m) & 1) a += (d == 1) ? ang[3 - m] : ang[11 - m];
        float zr, zi; __sincosf(a, &zi, &zr);
        Zv[d][v] = make_float2(zr, zi);
        if (v < 8) angT[d][v] = (d == 1) ? ang[11 - v] : ang[7 - v];
    }
    __syncthreads();

    // ---- merged per-wire factor: F = Rot0_q * (cos, sin)^T ----
    if (t < NQ) {
        const float c = cs[t].x, s = cs[t].y;
        const float* m = rot0[t];
        Fm[t] = make_float4(m[0] * c + m[2] * s,
                            m[1] * c + m[3] * s,
                            m[4] * c + m[6] * s,
                            m[5] * c + m[7] * s);
    }
    __syncthreads();

    // ---- init: post-layer0 product state scattered through layer-0 CNOT ring ----
    {
        float br, bi;
        {
            const float4 f = Fm[7];
            br = (t & 1) ? f.z : f.x;
            bi = (t & 1) ? f.w : f.y;
        }
#pragma unroll
        for (int k = 1; k < 8; ++k) {
            const float4 f = Fm[7 - k];
            const float fr = ((t >> k) & 1) ? f.z : f.x;
            const float fi = ((t >> k) & 1) ? f.w : f.y;
            const float nbr = br * fr - bi * fi;
            bi = br * fi + bi * fr;
            br = nbr;
        }
        float lr[4], li[4], hr[4], hi4[4];
        {
            const float4 fA = Fm[11], fB = Fm[10], fC = Fm[9], fD = Fm[8];
#pragma unroll
            for (int j = 0; j < 4; ++j) {
                const float ar = (j & 1) ? fA.z : fA.x, ai = (j & 1) ? fA.w : fA.y;
                const float br2 = (j & 2) ? fB.z : fB.x, bi2 = (j & 2) ? fB.w : fB.y;
                lr[j] = ar * br2 - ai * bi2;
                li[j] = ar * bi2 + ai * br2;
                const float cr = (j & 1) ? fC.z : fC.x, ci = (j & 1) ? fC.w : fC.y;
                const float dr = (j & 2) ? fD.z : fD.x, di = (j & 2) ? fD.w : fD.y;
                hr[j] = cr * dr - ci * di;
                hi4[j] = cr * di + ci * dr;
            }
        }
        int dT = 0;
#pragma unroll
        for (int k = 0; k < 8; ++k) dT ^= ((t >> k) & 1) ? C0T[k] : 0;
        const int sb0 = dT ^ ((dT >> 4) & 15);
#pragma unroll
        for (int v = 0; v < 16; ++v) {
            const float plr = lr[v & 3], pli = li[v & 3];
            const float phr = hr[v >> 2], phi2 = hi4[v >> 2];
            const float tr = plr * phr - pli * phi2;
            const float ti = plr * phi2 + pli * phr;
            st[sb0 ^ SLOTK0[v]] = make_float2(br * tr - bi * ti, br * ti + bi * tr);
        }
    }
    __syncthreads();

    float2 amp[16];

    // ===================== layer 1 =====================
    {   // stage A: p = t<<4 | v.  Dphi1 then RY wires 11..8
        const int base = t * 16, x4 = t & 15;
#pragma unroll
        for (int v = 0; v < 16; ++v) amp[v] = st[base + (v ^ x4)];
        apply_diag(amp, Zv[0], angT[0], t);
        apply4r<0>(amp, ry, 0);
#pragma unroll
        for (int v = 0; v < 16; ++v) st[base + (v ^ x4)] = amp[v];
    }
    __syncthreads();
    {   // stage B: RY wires 7..4
        const int hi = (t >> 4) * 256, x4 = t & 15;
#pragma unroll
        for (int v = 0; v < 16; ++v) amp[v] = st[hi + v * 16 + (x4 ^ v)];
        apply4r<1>(amp, ry, 0);
#pragma unroll
        for (int v = 0; v < 16; ++v) st[hi + v * 16 + (x4 ^ v)] = amp[v];
    }
    __syncthreads();
    {   // stage C: p = t | v<<8. RY wires 3..0, then Domega1, then C1 scatter
        const int slo = t ^ (t >> 4);
#pragma unroll
        for (int v = 0; v < 16; ++v) amp[v] = st[v * 256 + slo];
        apply4r<2>(amp, ry, 0);
        apply_diag(amp, Zv[1], angT[1], t);
        __syncthreads();
        int dT = 0;
#pragma unroll
        for (int j = 0; j < 8; ++j) dT ^= ((t >> j) & 1) ? C1T[j] : 0;
        const int sb1 = dT ^ ((dT >> 4) & 15);
#pragma unroll
        for (int v = 0; v < 16; ++v)
            st[sb1 ^ SLOTK1[v]] = amp[v];
        __syncthreads();
    }

    // ===================== layer 2 =====================
    {   // stage A: Dphi2 then RY wires 11..8
        const int base = t * 16, x4 = t & 15;
#pragma unroll
        for (int v = 0; v < 16; ++v) amp[v] = st[base + (v ^ x4)];
        apply_diag(amp, Zv[2], angT[2], t);
        apply4r<0>(amp, ry, 12);
#pragma unroll
        for (int v = 0; v < 16; ++v) st[base + (v ^ x4)] = amp[v];
    }
    __syncthreads();
    {   // stage B
        const int hi = (t >> 4) * 256, x4 = t & 15;
#pragma unroll
        for (int v = 0; v < 16; ++v) amp[v] = st[hi + v * 16 + (x4 ^ v)];
        apply4r<1>(amp, ry, 12);
#pragma unroll
        for (int v = 0; v < 16; ++v) st[hi + v * 16 + (x4 ^ v)] = amp[v];
    }
    __syncthreads();
    {   // stage C: RY wires 3..0; amps stay in regs (Domega2 dropped; C2 folded
        //          into measurement parity masks)
        const int slo = t ^ (t >> 4);
#pragma unroll
        for (int v = 0; v < 16; ++v) amp[v] = st[v * 256 + slo];
        apply4r<2>(amp, ry, 12);
    }

    // ---- probs in place ----
#pragma unroll
    for (int v = 0; v < 16; ++v)
        amp[v].x = amp[v].x * amp[v].x + amp[v].y * amp[v].y;

    // ---- PauliZ expectations via 5 Walsh coefficients of per-thread probs ----
    const float Pe = ((amp[0].x + amp[2].x) + (amp[4].x + amp[6].x))
                   + ((amp[8].x + amp[10].x) + (amp[12].x + amp[14].x));
    const float Po = ((amp[1].x + amp[3].x) + (amp[5].x + amp[7].x))
                   + ((amp[9].x + amp[11].x) + (amp[13].x + amp[15].x));
    const float w0 = Pe + Po;
    const float w1 = Pe - Po;
    const float A  = ((amp[0].x + amp[1].x) + (amp[4].x + amp[5].x))
                   + ((amp[8].x + amp[9].x) + (amp[12].x + amp[13].x));
    const float w2 = 2.f * A - w0;
    const float Bb = ((amp[0].x + amp[1].x) + (amp[2].x + amp[3].x))
                   + ((amp[8].x + amp[9].x) + (amp[10].x + amp[11].x));
    const float w4 = 2.f * Bb - w0;
    const float Cc = ((amp[0].x + amp[2].x) + (amp[4].x + amp[6].x))
                   + ((amp[9].x + amp[11].x) + (amp[13].x + amp[15].x));
    const float w9 = 2.f * Cc - w0;

    const int t0 = t & 1, t1 = (t >> 1) & 1, t2 = (t >> 2) & 1, t3 = (t >> 3) & 1;
    const int t4 = (t >> 4) & 1, t5 = (t >> 5) & 1, t6 = (t >> 6) & 1, t7 = (t >> 7) & 1;
    const int s24 = t2 ^ t5;
    const int s92 = t1 ^ t4 ^ t7;
    const int s49 = t0 ^ t3 ^ t6;
    const int s90 = t4 ^ t7;
    const int s48 = t3 ^ t6;

    float acc[NQ];
    acc[0]  = s24 ? -w1 : w1;
    acc[1]  = s92 ? -w0 : w0;
    acc[2]  = s49 ? -w0 : w0;
    acc[3]  = w9;
    acc[4]  = t7  ? -w4 : w4;
    acc[5]  = t6  ? -w2 : w2;
    acc[6]  = t5  ? -w9 : w9;
    acc[7]  = s90 ? -w4 : w4;
    acc[8]  = s48 ? -w2 : w2;
    acc[9]  = s24 ? -w9 : w9;
    acc[10] = s92 ? -w4 : w4;
    acc[11] = s49 ? -w2 : w2;

#pragma unroll
    for (int q = 0; q < NQ; ++q) {
        float vq = acc[q];
#pragma unroll
        for (int o = 16; o; o >>= 1) vq += __shfl_xor_sync(0xffffffffu, vq, o);
        if (lane == 0) red[warp][q] = vq;
    }
    __syncthreads();

    // ---- output head ----
    if (t < NCLASS) {
        float o = bo[t];
#pragma unroll
        for (int q = 0; q < NQ; ++q) {
            float z = 0.f;
#pragma unroll
            for (int w = 0; w < 8; ++w) z += red[w][q];
            o += z * Wo[t * NQ + q];
        }
        out[(size_t)b * NCLASS + t] = o;
    }
}

extern "C" void kernel_launch(void* const* d_in, const int* in_sizes, int n_in,
                              void* d_out, int out_size) {
    (void)in_sizes; (void)n_in; (void)out_size;
    const float* x       = (const float*)d_in[0];
    const float* Wp      = (const float*)d_in[1];
    const float* weights = (const float*)d_in[2];
    const float* Wo      = (const float*)d_in[3];
    const float* bo      = (const float*)d_in[4];

    qhead_kernel<<<BATCH, THREADS>>>(x, Wp, weights, Wo, bo, (float*)d_out);
}

// round 11
// speedup vs baseline: 1.1486x; 1.1480x over previous
#include <cuda_runtime.h>
#include <cstdint>

#define NQ      12
#define DIM     4096      // 2^12 amplitudes
#define THREADS 256
#define BATCH   4096
#define FEAT    768
#define NCLASS  10

// ---- compile-time GF(2) composites of the fixed CNOT rings ----
__device__ __constant__ const int C0T[8] = {0x81F,0x83F,0x87F,0x8FF,0x9FF,0xBFF,0xFFF,0x7FF};
static __device__ __constant__ const int SLOTK0[16] = {
    0x000,0x801,0x803,0x002,0x807,0x006,0x004,0x805,
    0x80F,0x00E,0x00C,0x80D,0x008,0x809,0x80B,0x00A};
__device__ __constant__ const int C1T[8] = {0x401,0x802,0x405,0x80A,0x415,0x82A,0x455,0x8AA};
static __device__ __constant__ const int SLOTK1[16] = {
    0x000,0x550,0xAA0,0xFF0,0x150,0x400,0xBF0,0xEA0,
    0x2A0,0x7F0,0x800,0xD50,0x3F0,0x6A0,0x950,0xC00};
// layer-2 measurement masks -> Walsh coeffs {0,1,2,4,9}.

// ---- tan-form RY gate sweep: 4 gates on local bits 0..3, 4 FFMA per pair ----
// RY(th) = cos(th/2) * [[1, -tau],[tau, 1]], tau = tan(th/2).
// The cos factors are folded (exactly, fp32) into the init state as a global
// scalar C = prod over all 24 gates, since every amp passes every gate once.
template <int STAGE>
__device__ __forceinline__ void apply4r(float2 amp[16], const float2 (&ry)[24], int lbase) {
#pragma unroll
    for (int g = 0; g < 4; ++g) {
        const int wire = 11 - (STAGE * 4 + g);
        const float tau = ry[lbase + wire].x;
        const int mask = 1 << g;
#pragma unroll
        for (int k = 0; k < 8; ++k) {
            const int h  = ((k & ~(mask - 1)) << 1) | (k & (mask - 1));
            const int h2 = h | mask;
            const float2 a = amp[h], b2 = amp[h2];
            amp[h].x  = a.x  - tau * b2.x;
            amp[h].y  = a.y  - tau * b2.y;
            amp[h2].x = b2.x + tau * a.x;
            amp[h2].y = b2.y + tau * a.y;
        }
    }
}

// ---- product-diagonal application at a direct-index point ----
__device__ __forceinline__ void apply_diag(float2 amp[16], const float2* Zv,
                                           const float* angT, int t) {
    float a = 0.f;
#pragma unroll
    for (int k = 0; k < 8; ++k) a += ((t >> k) & 1) ? angT[k] : 0.f;
    float zr, zi; __sincosf(a, &zi, &zr);
#pragma unroll
    for (int v = 0; v < 16; ++v) {
        const float2 z = Zv[v];                 // broadcast LDS
        const float wr = zr * z.x - zi * z.y;
        const float wi = zr * z.y + zi * z.x;
        const float nx = amp[v].x * wr - amp[v].y * wi;
        amp[v].y = amp[v].x * wi + amp[v].y * wr;
        amp[v].x = nx;
    }
}

__global__ __launch_bounds__(THREADS, 3)
void qhead_kernel(const float* __restrict__ x,
                  const float* __restrict__ Wp,
                  const float* __restrict__ weights,
                  const float* __restrict__ Wo,
                  const float* __restrict__ bo,
                  float* __restrict__ out)
{
    __shared__ float2 st[DIM];          // swizzled state: slot(p) = p ^ ((p>>4)&15)
    __shared__ float2 cs[NQ];           // (cos(a/2), sin(a/2)) per wire
    __shared__ float  rot0[NQ][8];      // layer-0 Rot matrices (for init fold only)
    __shared__ float4 Fm[NQ];           // merged per-wire factor Rot0 * RY(a) |0>
    __shared__ float2 ry[24];           // (tan(th/2), cos(th/2)) for layers 1,2
    __shared__ float2 Zv[3][16];        // diagonal v-part tables (incl. base phase)
    __shared__ float  angT[3][8];       // diagonal t-part angles
    __shared__ float  red[8][NQ];       // cross-warp reduction buffer

    const int t    = threadIdx.x;
    const int b    = blockIdx.x;
    const int lane = t & 31;
    const int warp = t >> 5;

    // ---- angle encoding: 12 dot products (float4), tanh, half-angle sincos ----
    {
        const float4* xr4  = (const float4*)(x + (size_t)b * FEAT);
        const int q0 = warp;
        const bool two = (warp < 4);
        const float4* wp04 = (const float4*)(Wp + q0 * FEAT);
        const float4* wp14 = (const float4*)(Wp + (q0 + 8) * FEAT);
        float d0 = 0.f, d1 = 0.f;
#pragma unroll
        for (int i = lane; i < FEAT / 4; i += 32) {
            const float4 xv = xr4[i];
            const float4 a  = wp04[i];
            d0 += xv.x * a.x + xv.y * a.y + xv.z * a.z + xv.w * a.w;
            if (two) {
                const float4 c = wp14[i];
                d1 += xv.x * c.x + xv.y * c.y + xv.z * c.z + xv.w * c.w;
            }
        }
#pragma unroll
        for (int o = 16; o; o >>= 1) {
            d0 += __shfl_xor_sync(0xffffffffu, d0, o);
            d1 += __shfl_xor_sync(0xffffffffu, d1, o);
        }
        if (lane == 0) {
            float th = tanhf(d0) * 0.7853981633974483f;   // a/2
            float c, s; __sincosf(th, &s, &c);
            cs[q0] = make_float2(c, s);
            if (two) {
                float th1 = tanhf(d1) * 0.7853981633974483f;
                float c1, s1; __sincosf(th1, &s1, &c1);
                cs[q0 + 8] = make_float2(c1, s1);
            }
        }
    }

    // ---- layer-0 Rot matrices (full, for init fold) ----
    if (t < NQ) {
        const float phi = weights[t * 3 + 0];
        const float th  = weights[t * 3 + 1];
        const float om  = weights[t * 3 + 2];
        float c, s; __sincosf(0.5f * th, &s, &c);
        const float aa = 0.5f * (phi + om);
        const float bb = 0.5f * (phi - om);
        float sa, ca, sb, cb;
        __sincosf(aa, &sa, &ca);
        __sincosf(bb, &sb, &cb);
        rot0[t][0] =  c * ca;  rot0[t][1] = -c * sa;   // m00
        rot0[t][2] = -s * cb;  rot0[t][3] = -s * sb;   // m01
        rot0[t][4] =  s * cb;  rot0[t][5] = -s * sb;   // m10
        rot0[t][6] =  c * ca;  rot0[t][7] =  c * sa;   // m11
    }

    // ---- RY (tau, c) for layers 1,2 ----
    if (t < 24) {
        const int l = 1 + t / 12, q = t % 12;
        const float th = weights[(l * 12 + q) * 3 + 1];
        float c, s; __sincosf(0.5f * th, &s, &c);
        ry[t] = make_float2(s / c, c);
    }

    // ---- diagonal tables: d=0 -> phi(l1), d=1 -> omega(l1), d=2 -> phi(l2) ----
    if (t < 48) {
        const int d = t >> 4, v = t & 15;
        const int l = (d == 2) ? 2 : 1;
        const int j = (d == 1) ? 2 : 0;
        float ang[12];
        float sum = 0.f;
#pragma unroll
        for (int q = 0; q < 12; ++q) { ang[q] = weights[(l * 12 + q) * 3 + j]; sum += ang[q]; }
        float a = -0.5f * sum;
#pragma unroll
        for (int m = 0; m < 4; ++m)
            if ((v >> m) & 1) a += (d == 1) ? ang[3 - m] : ang[11 - m];
        float zr, zi; __sincosf(a, &zi, &zr);
        Zv[d][v] = make_float2(zr, zi);
        if (v < 8) angT[d][v] = (d == 1) ? ang[11 - v] : ang[7 - v];
    }
    __syncthreads();

    // ---- merged per-wire factor: F = Rot0_q * (cos, sin)^T ----
    // Thread 0 additionally folds the global tan-form scale C = prod(ry[g].y)
    // into Fm[0] (every amp uses exactly one entry of Fm[0]).
    if (t < NQ) {
        const float c = cs[t].x, s = cs[t].y;
        const float* m = rot0[t];
        float f0 = m[0] * c + m[2] * s;
        float f1 = m[1] * c + m[3] * s;
        float f2 = m[4] * c + m[6] * s;
        float f3 = m[5] * c + m[7] * s;
        if (t == 0) {
            float C = 1.f;
#pragma unroll
            for (int g = 0; g < 24; ++g) C *= ry[g].y;
            f0 *= C; f1 *= C; f2 *= C; f3 *= C;
        }
        Fm[t] = make_float4(f0, f1, f2, f3);
    }
    __syncthreads();

    // ---- init: post-layer0 product state scattered through layer-0 CNOT ring ----
    {
        float br, bi;
        {
            const float4 f = Fm[7];
            br = (t & 1) ? f.z : f.x;
            bi = (t & 1) ? f.w : f.y;
        }
#pragma unroll
        for (int k = 1; k < 8; ++k) {
            const float4 f = Fm[7 - k];
            const float fr = ((t >> k) & 1) ? f.z : f.x;
            const float fi = ((t >> k) & 1) ? f.w : f.y;
            const float nbr = br * fr - bi * fi;
            bi = br * fi + bi * fr;
            br = nbr;
        }
        float lr[4], li[4], hr[4], hi4[4];
        {
            const float4 fA = Fm[11], fB = Fm[10], fC = Fm[9], fD = Fm[8];
#pragma unroll
            for (int j = 0; j < 4; ++j) {
                const float ar = (j & 1) ? fA.z : fA.x, ai = (j & 1) ? fA.w : fA.y;
                const float br2 = (j & 2) ? fB.z : fB.x, bi2 = (j & 2) ? fB.w : fB.y;
                lr[j] = ar * br2 - ai * bi2;
                li[j] = ar * bi2 + ai * br2;
                const float cr = (j & 1) ? fC.z : fC.x, ci = (j & 1) ? fC.w : fC.y;
                const float dr = (j & 2) ? fD.z : fD.x, di = (j & 2) ? fD.w : fD.y;
                hr[j] = cr * dr - ci * di;
                hi4[j] = cr * di + ci * dr;
            }
        }
        int dT = 0;
#pragma unroll
        for (int k = 0; k < 8; ++k) dT ^= ((t >> k) & 1) ? C0T[k] : 0;
        const int sb0 = dT ^ ((dT >> 4) & 15);
#pragma unroll
        for (int v = 0; v < 16; ++v) {
            const float plr = lr[v & 3], pli = li[v & 3];
            const float phr = hr[v >> 2], phi2 = hi4[v >> 2];
            const float tr = plr * phr - pli * phi2;
            const float ti = plr * phi2 + pli * phr;
            st[sb0 ^ SLOTK0[v]] = make_float2(br * tr - bi * ti, br * ti + bi * tr);
        }
    }
    __syncthreads();

    float2 amp[16];

    // ===================== layer 1 =====================
    {   // stage A: p = t<<4 | v.  Dphi1 then RY wires 11..8
        const int base = t * 16, x4 = t & 15;
#pragma unroll
        for (int v = 0; v < 16; ++v) amp[v] = st[base + (v ^ x4)];
        apply_diag(amp, Zv[0], angT[0], t);
        apply4r<0>(amp, ry, 0);
#pragma unroll
        for (int v = 0; v < 16; ++v) st[base + (v ^ x4)] = amp[v];
    }
    __syncwarp();   // A->B boundary stays within an aligned 16-thread group
    {   // stage B: RY wires 7..4
        const int hi = (t >> 4) * 256, x4 = t & 15;
#pragma unroll
        for (int v = 0; v < 16; ++v) amp[v] = st[hi + v * 16 + (x4 ^ v)];
        apply4r<1>(amp, ry, 0);
#pragma unroll
        for (int v = 0; v < 16; ++v) st[hi + v * 16 + (x4 ^ v)] = amp[v];
    }
    __syncthreads();
    {   // stage C: p = t | v<<8. RY wires 3..0, then Domega1, then C1 scatter
        const int slo = t ^ (t >> 4);
#pragma unroll
        for (int v = 0; v < 16; ++v) amp[v] = st[v * 256 + slo];
        apply4r<2>(amp, ry, 0);
        apply_diag(amp, Zv[1], angT[1], t);
        __syncthreads();
        int dT = 0;
#pragma unroll
        for (int j = 0; j < 8; ++j) dT ^= ((t >> j) & 1) ? C1T[j] : 0;
        const int sb1 = dT ^ ((dT >> 4) & 15);
#pragma unroll
        for (int v = 0; v < 16; ++v)
            st[sb1 ^ SLOTK1[v]] = amp[v];
        __syncthreads();
    }

    // ===================== layer 2 =====================
    {   // stage A: Dphi2 then RY wires 11..8
        const int base = t * 16, x4 = t & 15;
#pragma unroll
        for (int v = 0; v < 16; ++v) amp[v] = st[base + (v ^ x4)];
        apply_diag(amp, Zv[2], angT[2], t);
        apply4r<0>(amp, ry, 12);
#pragma unroll
        for (int v = 0; v < 16; ++v) st[base + (v ^ x4)] = amp[v];
    }
    __syncwarp();   // A->B boundary stays within an aligned 16-thread group
    {   // stage B
        const int hi = (t >> 4) * 256, x4 = t & 15;
#pragma unroll
        for (int v = 0; v < 16; ++v) amp[v] = st[hi + v * 16 + (x4 ^ v)];
        apply4r<1>(amp, ry, 12);
#pragma unroll
        for (int v = 0; v < 16; ++v) st[hi + v * 16 + (x4 ^ v)] = amp[v];
    }
    __syncthreads();
    {   // stage C: RY wires 3..0; amps stay in regs (Domega2 dropped; C2 folded
        //          into measurement parity masks)
        const int slo = t ^ (t >> 4);
#pragma unroll
        for (int v = 0; v < 16; ++v) amp[v] = st[v * 256 + slo];
        apply4r<2>(amp, ry, 12);
    }

    // ---- probs in place ----
#pragma unroll
    for (int v = 0; v < 16; ++v)
        amp[v].x = amp[v].x * amp[v].x + amp[v].y * amp[v].y;

    // ---- PauliZ expectations via 5 Walsh coefficients of per-thread probs ----
    const float Pe = ((amp[0].x + amp[2].x) + (amp[4].x + amp[6].x))
                   + ((amp[8].x + amp[10].x) + (amp[12].x + amp[14].x));
    const float Po = ((amp[1].x + amp[3].x) + (amp[5].x + amp[7].x))
                   + ((amp[9].x + amp[11].x) + (amp[13].x + amp[15].x));
    const float w0 = Pe + Po;
    const float w1 = Pe - Po;
    const float A  = ((amp[0].x + amp[1].x) + (amp[4].x + amp[5].x))
                   + ((amp[8].x + amp[9].x) + (amp[12].x + amp[13].x));
    const float w2 = 2.f * A - w0;
    const float Bb = ((amp[0].x + amp[1].x) + (amp[2].x + amp[3].x))
                   + ((amp[8].x + amp[9].x) + (amp[10].x + amp[11].x));
    const float w4 = 2.f * Bb - w0;
    const float Cc = ((amp[0].x + amp[2].x) + (amp[4].x + amp[6].x))
                   + ((amp[9].x + amp[11].x) + (amp[13].x + amp[15].x));
    const float w9 = 2.f * Cc - w0;

    const int t0 = t & 1, t1 = (t >> 1) & 1, t2 = (t >> 2) & 1, t3 = (t >> 3) & 1;
    const int t4 = (t >> 4) & 1, t5 = (t >> 5) & 1, t6 = (t >> 6) & 1, t7 = (t >> 7) & 1;
    const int s24 = t2 ^ t5;
    const int s92 = t1 ^ t4 ^ t7;
    const int s49 = t0 ^ t3 ^ t6;
    const int s90 = t4 ^ t7;
    const int s48 = t3 ^ t6;

    float acc[NQ];
    acc[0]  = s24 ? -w1 : w1;
    acc[1]  = s92 ? -w0 : w0;
    acc[2]  = s49 ? -w0 : w0;
    acc[3]  = w9;
    acc[4]  = t7  ? -w4 : w4;
    acc[5]  = t6  ? -w2 : w2;
    acc[6]  = t5  ? -w9 : w9;
    acc[7]  = s90 ? -w4 : w4;
    acc[8]  = s48 ? -w2 : w2;
    acc[9]  = s24 ? -w9 : w9;
    acc[10] = s92 ? -w4 : w4;
    acc[11] = s49 ? -w2 : w2;

#pragma unroll
    for (int q = 0; q < NQ; ++q) {
        float vq = acc[q];
#pragma unroll
        for (int o = 16; o; o >>= 1) vq += __shfl_xor_sync(0xffffffffu, vq, o);
        if (lane == 0) red[warp][q] = vq;
    }
    __syncthreads();

    // ---- output head ----
    if (t < NCLASS) {
        float o = bo[t];
#pragma unroll
        for (int q = 0; q < NQ; ++q) {
            float z = 0.f;
#pragma unroll
            for (int w = 0; w < 8; ++w) z += red[w][q];
            o += z * Wo[t * NQ + q];
        }
        out[(size_t)b * NCLASS + t] = o;
    }
}

extern "C" void kernel_launch(void* const* d_in, const int* in_sizes, int n_in,
                              void* d_out, int out_size) {
    (void)in_sizes; (void)n_in; (void)out_size;
    const float* x       = (const float*)d_in[0];
    const float* Wp      = (const float*)d_in[1];
    const float* weights = (const float*)d_in[2];
    const float* Wo      = (const float*)d_in[3];
    const float* bo      = (const float*)d_in[4];

    qhead_kernel<<<BATCH, THREADS>>>(x, Wp, weights, Wo, bo, (float*)d_out);
}